// round 11
// baseline (speedup 1.0000x reference)
#include <cuda_runtime.h>
#include <cuda_bf16.h>

#define NN 50000
#define EE 800000
#define IC  128
#define OC  64
#define TILES ((NN + 63) / 64)        // 782 gemm tiles
#define BUILD_BLOCKS 56
#define GEMM_BLOCKS  388
#define GRID (BUILD_BLOCKS + GEMM_BLOCKS)   // 444 = 148 * 3 -> one wave
#define SCAN_BLOCKS 49                // 49 * 1024 >= NN

// ---- scratch (no device allocations; zero-initialized at module load) ----
__device__ __align__(16) float g_h[NN * OC];
__device__ float g_adst[NN];
__device__ float g_asrc[NN];
__device__ float g_esum[NN];      // zeros on entry; reset by k6b
__device__ int   g_deg[NN];       // zeros on entry; restored during scan
__device__ int   g_ptr[NN + 1];
__device__ int   g_cursor[NN];
__device__ __align__(16) float2 g_cw[EE];   // per CSR slot: {src (bits), weight}
__device__ int   g_agg[64];
__device__ int   g_barcnt[3];     // build barrier counters (reset by k6b)
__device__ int   g_barrel[3];     // build barrier release flags (reset by k6b)

// int64-layout sniff: ids < 2^31 => odd 32-bit words all zero
__device__ __forceinline__ bool sniff64(const int* ei32) {
    int z = (ei32[1] == 0) + (ei32[3] == 0) + (ei32[5] == 0) +
            (ei32[7] == 0) + (ei32[9] == 0) + (ei32[11] == 0);
    return z == 6;
}

// barrier among the BUILD_BLOCKS build blocks (all resident => safe spin)
__device__ __forceinline__ void build_barrier(int id) {
    __syncthreads();
    if (threadIdx.x == 0) {
        __threadfence();
        int prev = atomicAdd(&g_barcnt[id], 1);
        if (prev == BUILD_BLOCKS - 1) {
            __threadfence();
            atomicExch(&g_barrel[id], 1);
        }
        while (atomicAdd(&g_barrel[id], 0) == 0) { }
        __threadfence();
    }
    __syncthreads();
}

// packed fp32x2 FMA: d = a * b + d  (sm_100+)
__device__ __forceinline__ void ffma2(unsigned long long& d,
                                      unsigned long long a,
                                      unsigned long long b) {
    asm("fma.rn.f32x2 %0, %1, %2, %0;" : "+l"(d) : "l"(a), "l"(b));
}
__device__ __forceinline__ unsigned long long dup2(float v) {
    unsigned long long p;
    unsigned int b = __float_as_uint(v);
    asm("mov.b64 %0, {%1, %2};" : "=l"(p) : "r"(b), "r"(b));
    return p;
}
__device__ __forceinline__ float2 unpack2(unsigned long long p) {
    unsigned int lo, hi;
    asm("mov.b64 {%0, %1}, %2;" : "=r"(lo), "=r"(hi) : "l"(p));
    return make_float2(__uint_as_float(lo), __uint_as_float(hi));
}

// ============================================================
// MEGA: blocks [0,56) hist+scan; blocks [56,444) GEMM
// (h = x@W + fused attention dots), f32x2-packed FMAs.
// ============================================================
__global__ __launch_bounds__(256, 3) void mega(
    const float* __restrict__ x, const float* __restrict__ W,
    const float* __restrict__ att, const int* __restrict__ ei32)
{
    __shared__ float Ws[64][64];
    __shared__ float Xs[64][68];
    __shared__ int   ish[128];
    const int tid = threadIdx.x;
    const int bid = blockIdx.x;

    if (bid < BUILD_BLOCKS) {
        // ---------------- build role: hist + scan ----------------
        const bool is64 = sniff64(ei32);

        // Phase A: in-degree histogram
        for (int e = bid * 256 + tid; e < EE; e += BUILD_BLOCKS * 256) {
            int d = is64 ? ei32[2 * (EE + e)] : ei32[EE + e];
            d = min(max(d, 0), NN - 1);
            atomicAdd(&g_deg[d], 1);
        }
        build_barrier(0);

        // Phase B1: local scan (blocks 0..48, 1024 elems each, 4/thread)
        int vv[4] = {0, 0, 0, 0};
        int local_excl = 0;
        const int i0 = bid * 1024 + tid * 4;
        if (bid < SCAN_BLOCKS) {
            const int lane = tid & 31, wid = tid >> 5;
#pragma unroll
            for (int j = 0; j < 4; j++) {
                int idx = i0 + j;
                if (idx < NN) { vv[j] = g_deg[idx]; g_deg[idx] = 0; }
            }
            int ts = (vv[0] + vv[1]) + (vv[2] + vv[3]);
            int s = ts;
#pragma unroll
            for (int o = 1; o < 32; o <<= 1) {
                int t = __shfl_up_sync(0xffffffffu, s, o);
                if (lane >= o) s += t;
            }
            if (lane == 31) ish[wid] = s;
            __syncthreads();
            if (wid == 0 && lane < 8) {
                int ws = ish[lane];
#pragma unroll
                for (int o = 1; o < 8; o <<= 1) {
                    int t = __shfl_up_sync(0x000000ffu, ws, o);
                    if (lane >= o) ws += t;
                }
                ish[lane] = ws;
            }
            __syncthreads();
            local_excl = (s - ts) + ((wid > 0) ? ish[wid - 1] : 0);
            if (tid == 0) g_agg[bid] = ish[7];   // single writer
            __syncthreads();
        }
        build_barrier(1);

        // Phase B2: cross-block prefix + write ptr/cursor
        if (bid < SCAN_BLOCKS) {
            if (tid < 64) ish[tid] = (tid < bid) ? g_agg[tid] : 0;
            __syncthreads();
#pragma unroll
            for (int o = 32; o > 0; o >>= 1) {
                if (tid < o) ish[tid] += ish[tid + o];
                __syncthreads();
            }
            int run = ish[0] + local_excl;
#pragma unroll
            for (int j = 0; j < 4; j++) {
                int idx = i0 + j;
                if (idx < NN) { g_ptr[idx] = run; g_cursor[idx] = run; run += vv[j]; }
            }
            if (bid == 0 && tid == 0) g_ptr[NN] = EE;
        }
    } else {
        // ---------------- gemm role ----------------
        const int tx = tid & 15;
        const int ty = tid >> 4;

        float att_d[4], att_s[4];
#pragma unroll
        for (int j = 0; j < 4; j++) {
            att_d[j] = att[tx * 4 + j];
            att_s[j] = att[64 + tx * 4 + j];
        }

        for (int tile = bid - BUILD_BLOCKS; tile < TILES; tile += GEMM_BLOCKS) {
            const int n0 = tile * 64;
            unsigned long long accp[4][2];
#pragma unroll
            for (int i = 0; i < 4; i++) { accp[i][0] = 0ull; accp[i][1] = 0ull; }

            for (int kc = 0; kc < IC; kc += 64) {
                for (int i = tid; i < 64 * 64; i += 256) {
                    int k = i >> 6, c = i & 63;
                    Ws[k][c] = W[(kc + k) * OC + c];
                }
                for (int i = tid; i < 64 * 64; i += 256) {
                    int r = i >> 6, k = i & 63;
                    int n = n0 + r;
                    Xs[k][r] = (n < NN) ? x[n * IC + kc + k] : 0.f;
                }
                __syncthreads();
#pragma unroll
                for (int k = 0; k < 64; k++) {
                    float4 xv = *(const float4*)&Xs[k][ty * 4];
                    const unsigned long long* wp =
                        (const unsigned long long*)&Ws[k][tx * 4];
                    unsigned long long w0 = wp[0], w1 = wp[1];
                    unsigned long long x0 = dup2(xv.x);
                    unsigned long long x1 = dup2(xv.y);
                    unsigned long long x2 = dup2(xv.z);
                    unsigned long long x3 = dup2(xv.w);
                    ffma2(accp[0][0], x0, w0); ffma2(accp[0][1], x0, w1);
                    ffma2(accp[1][0], x1, w0); ffma2(accp[1][1], x1, w1);
                    ffma2(accp[2][0], x2, w0); ffma2(accp[2][1], x2, w1);
                    ffma2(accp[3][0], x3, w0); ffma2(accp[3][1], x3, w1);
                }
                __syncthreads();
            }

#pragma unroll
            for (int i = 0; i < 4; i++) {
                float2 p0 = unpack2(accp[i][0]);
                float2 p1 = unpack2(accp[i][1]);
                int n = n0 + ty * 4 + i;
                if (n < NN) {
                    float4 v = make_float4(p0.x, p0.y, p1.x, p1.y);
                    *(float4*)(g_h + n * OC + tx * 4) = v;
                }
                float pd = p0.x * att_d[0] + p0.y * att_d[1] +
                           p1.x * att_d[2] + p1.y * att_d[3];
                float ps = p0.x * att_s[0] + p0.y * att_s[1] +
                           p1.x * att_s[2] + p1.y * att_s[3];
#pragma unroll
                for (int o = 8; o > 0; o >>= 1) {
                    pd += __shfl_down_sync(0xffffffffu, pd, o, 16);
                    ps += __shfl_down_sync(0xffffffffu, ps, o, 16);
                }
                if (tx == 0 && n < NN) {
                    g_adst[n] = pd;
                    g_asrc[n] = ps;
                }
            }
        }
    }
}

// ============================================================
// K6a: edge-parallel fill + weight + softmax denominator.
// g_cw[pos] = {src bits, w};  esum[d] += w.
// ============================================================
__global__ void k6a_fill(const int* __restrict__ ei32) {
    int e = blockIdx.x * blockDim.x + threadIdx.x;
    if (e >= EE) return;
    const bool is64 = sniff64(ei32);
    int s, d;
    if (is64) { s = ei32[2 * e]; d = ei32[2 * (EE + e)]; }
    else      { s = ei32[e];     d = ei32[EE + e]; }
    s = min(max(s, 0), NN - 1);
    d = min(max(d, 0), NN - 1);
    float a = g_adst[d] + g_asrc[s];
    a = (a > 0.f) ? a : 0.2f * a;
    float w = __expf(a);
    int pos = atomicAdd(&g_cursor[d], 1);
    g_cw[pos] = make_float2(__int_as_float(s), w);
    atomicAdd(&g_esum[d], w);
}

// ============================================================
// K6b: gather stream. warp/node; per edge: one uniform LDG.64
// {s,w} + one LDG.64 h + 2 FFMA. No shfl in the hot loop.
// Resets esum and mega barrier state for next replay.
// ============================================================
__global__ void k6b_gather(const float* __restrict__ bias, float* __restrict__ out) {
    if (blockIdx.x == 0 && threadIdx.x < 3) {
        g_barcnt[threadIdx.x] = 0;
        g_barrel[threadIdx.x] = 0;
    }
    const int lane = threadIdx.x & 31;
    const int n = blockIdx.x * 8 + (threadIdx.x >> 5);
    if (n >= NN) return;

    float es = g_esum[n];
    __syncwarp();
    if (lane == 0) g_esum[n] = 0.f;   // restore invariant

    // self loop
    float al = g_adst[n] + g_asrc[n];
    al = (al > 0.f) ? al : 0.2f * al;
    float wself = __expf(al);
    float2 hv = *(const float2*)(g_h + n * OC + lane * 2);
    float wsum = es + wself;
    float a0 = wself * hv.x, a1 = wself * hv.y;
    float b0 = 0.f, b1 = 0.f, c0 = 0.f, c1 = 0.f, d0 = 0.f, d1 = 0.f;

    const int beg = g_ptr[n];
    const int end = g_ptr[n + 1];
    int i = beg;
    for (; i + 3 < end; i += 4) {
        float2 cw0 = g_cw[i];
        float2 cw1 = g_cw[i + 1];
        float2 cw2 = g_cw[i + 2];
        float2 cw3 = g_cw[i + 3];
        int s0 = __float_as_int(cw0.x);
        int s1 = __float_as_int(cw1.x);
        int s2 = __float_as_int(cw2.x);
        int s3 = __float_as_int(cw3.x);
        float2 h0 = *(const float2*)(g_h + s0 * OC + lane * 2);
        float2 h1 = *(const float2*)(g_h + s1 * OC + lane * 2);
        float2 h2 = *(const float2*)(g_h + s2 * OC + lane * 2);
        float2 h3 = *(const float2*)(g_h + s3 * OC + lane * 2);
        a0 += cw0.y * h0.x; a1 += cw0.y * h0.y;
        b0 += cw1.y * h1.x; b1 += cw1.y * h1.y;
        c0 += cw2.y * h2.x; c1 += cw2.y * h2.y;
        d0 += cw3.y * h3.x; d1 += cw3.y * h3.y;
    }
    for (; i < end; i++) {
        float2 cw = g_cw[i];
        int s = __float_as_int(cw.x);
        float2 h2 = *(const float2*)(g_h + s * OC + lane * 2);
        a0 += cw.y * h2.x; a1 += cw.y * h2.y;
    }
    a0 = (a0 + b0) + (c0 + d0);
    a1 = (a1 + b1) + (c1 + d1);

    const float2 bv = *(const float2*)(bias + lane * 2);
    float inv_s = 1.0f / (wsum + 1e-16f);
    float v0 = a0 * inv_s + bv.x;
    float v1 = a1 * inv_s + bv.y;

    float ss = v0 * v0 + v1 * v1;
#pragma unroll
    for (int o = 16; o > 0; o >>= 1) ss += __shfl_xor_sync(0xffffffffu, ss, o);
    float inv = 1.0f / fmaxf(sqrtf(ss), 1e-12f);
    *(float2*)(out + n * OC + lane * 2) = make_float2(v0 * inv, v1 * inv);
}

extern "C" void kernel_launch(void* const* d_in, const int* in_sizes, int n_in,
                              void* d_out, int out_size) {
    const float* x = (const float*)d_in[0];
    const int* ei32 = (const int*)d_in[1];   // dtype sniffed on device
    const float* W = (const float*)d_in[2];
    const float* att = (const float*)d_in[3];
    const float* bias = (const float*)d_in[4];
    float* out = (float*)d_out;

    mega<<<GRID, 256>>>(x, W, att, ei32);
    k6a_fill<<<(EE + 255) / 256, 256>>>(ei32);
    k6b_gather<<<(NN + 7) / 8, 256>>>(bias, out);
}

// round 12
// speedup vs baseline: 2.1275x; 2.1275x over previous
#include <cuda_runtime.h>
#include <cuda_bf16.h>

#define NN 50000
#define EE 800000
#define IC  128
#define OC  64
#define TILES ((NN + 63) / 64)        // 782 gemm tiles
#define BUILD_BLOCKS 112
#define GEMM_BLOCKS  332
#define GRID (BUILD_BLOCKS + GEMM_BLOCKS)   // 444 = 148 * 3 -> one wave
#define SCAN_BLOCKS 98                // 98 * 512 >= NN

// ---- scratch (no device allocations; zero-initialized at module load) ----
__device__ __align__(16) float g_h[NN * OC];
__device__ float g_adst[NN];
__device__ float g_asrc[NN];
__device__ int   g_deg[NN];       // zeros on entry; restored during scan
__device__ int   g_ptr[NN + 1];
__device__ int   g_cursor[NN];
__device__ int   g_col[EE];
__device__ int   g_agg[128];
__device__ int   g_barcnt[3];     // build barrier counters (reset by k6)
__device__ int   g_barrel[3];     // build barrier release flags (reset by k6)

// int64-layout sniff: ids < 2^31 => odd 32-bit words all zero
__device__ __forceinline__ bool sniff64(const int* ei32) {
    int z = (ei32[1] == 0) + (ei32[3] == 0) + (ei32[5] == 0) +
            (ei32[7] == 0) + (ei32[9] == 0) + (ei32[11] == 0);
    return z == 6;
}

// barrier among the BUILD_BLOCKS build blocks (all resident => safe spin)
__device__ __forceinline__ void build_barrier(int id) {
    __syncthreads();
    if (threadIdx.x == 0) {
        __threadfence();
        int prev = atomicAdd(&g_barcnt[id], 1);
        if (prev == BUILD_BLOCKS - 1) {
            __threadfence();
            atomicExch(&g_barrel[id], 1);
        }
        while (atomicAdd(&g_barrel[id], 0) == 0) { }
        __threadfence();
    }
    __syncthreads();
}

// packed fp32x2 FMA: d = a * b + d  (sm_100+)
__device__ __forceinline__ void ffma2(unsigned long long& d,
                                      unsigned long long a,
                                      unsigned long long b) {
    asm("fma.rn.f32x2 %0, %1, %2, %0;" : "+l"(d) : "l"(a), "l"(b));
}
__device__ __forceinline__ unsigned long long dup2(float v) {
    unsigned long long p;
    unsigned int b = __float_as_uint(v);
    asm("mov.b64 %0, {%1, %2};" : "=l"(p) : "r"(b), "r"(b));
    return p;
}
__device__ __forceinline__ float2 unpack2(unsigned long long p) {
    unsigned int lo, hi;
    asm("mov.b64 {%0, %1}, %2;" : "=r"(lo), "=r"(hi) : "l"(p));
    return make_float2(__uint_as_float(lo), __uint_as_float(hi));
}

// ============================================================
// MEGA: blocks [0,112) build full CSR; blocks [112,444) GEMM
// (h = x@W + fused attention dots), f32x2-packed FMAs.
// (reverted to the 78.6us-proven structure)
// ============================================================
__global__ __launch_bounds__(256, 3) void mega(
    const float* __restrict__ x, const float* __restrict__ W,
    const float* __restrict__ att, const int* __restrict__ ei32)
{
    __shared__ float Ws[64][64];
    __shared__ float Xs[64][68];
    __shared__ int   ish[128];
    const int tid = threadIdx.x;
    const int bid = blockIdx.x;

    if (bid < BUILD_BLOCKS) {
        // ---------------- build role ----------------
        const bool is64 = sniff64(ei32);

        // Phase A: in-degree histogram
        for (int e = bid * 256 + tid; e < EE; e += BUILD_BLOCKS * 256) {
            int d = is64 ? ei32[2 * (EE + e)] : ei32[EE + e];
            d = min(max(d, 0), NN - 1);
            atomicAdd(&g_deg[d], 1);
        }
        build_barrier(0);

        // Phase B1: local exclusive scan (blocks 0..97, 512 elems each)
        int v0 = 0, v1 = 0, local_excl = 0;
        int i0 = 0, i1 = 0;
        if (bid < SCAN_BLOCKS) {
            const int lane = tid & 31, wid = tid >> 5;
            i0 = bid * 512 + 2 * tid;
            i1 = i0 + 1;
            v0 = (i0 < NN) ? g_deg[i0] : 0;
            v1 = (i1 < NN) ? g_deg[i1] : 0;
            if (i0 < NN) g_deg[i0] = 0;    // restore invariant
            if (i1 < NN) g_deg[i1] = 0;
            int ts = v0 + v1, s = ts;
#pragma unroll
            for (int o = 1; o < 32; o <<= 1) {
                int t = __shfl_up_sync(0xffffffffu, s, o);
                if (lane >= o) s += t;
            }
            if (lane == 31) ish[wid] = s;
            __syncthreads();
            if (wid == 0 && lane < 8) {
                int ws = ish[lane];
#pragma unroll
                for (int o = 1; o < 8; o <<= 1) {
                    int t = __shfl_up_sync(0x000000ffu, ws, o);
                    if (lane >= o) ws += t;
                }
                ish[lane] = ws;
            }
            __syncthreads();
            local_excl = (s - ts) + ((wid > 0) ? ish[wid - 1] : 0);
            if (tid == 0) g_agg[bid] = ish[7];   // single writer
            __syncthreads();
        }
        build_barrier(1);

        // Phase B2: cross-block prefix + write ptr/cursor
        if (bid < SCAN_BLOCKS) {
            if (tid < 128) ish[tid] = (tid < bid) ? g_agg[tid] : 0;
            __syncthreads();
#pragma unroll
            for (int o = 64; o > 0; o >>= 1) {
                if (tid < o) ish[tid] += ish[tid + o];
                __syncthreads();
            }
            const int prefix = ish[0];
            int e0 = prefix + local_excl;
            if (i0 < NN) { g_ptr[i0] = e0;      g_cursor[i0] = e0; }
            if (i1 < NN) { g_ptr[i1] = e0 + v0; g_cursor[i1] = e0 + v0; }
            if (bid == 0 && tid == 0) g_ptr[NN] = EE;
        }
        build_barrier(2);

        // Phase C: fill CSR columns
        for (int e = bid * 256 + tid; e < EE; e += BUILD_BLOCKS * 256) {
            int s, d;
            if (is64) { s = ei32[2 * e]; d = ei32[2 * (EE + e)]; }
            else      { s = ei32[e];     d = ei32[EE + e]; }
            s = min(max(s, 0), NN - 1);
            d = min(max(d, 0), NN - 1);
            int pos = atomicAdd(&g_cursor[d], 1);
            g_col[pos] = s;
        }
    } else {
        // ---------------- gemm role ----------------
        const int tx = tid & 15;
        const int ty = tid >> 4;

        float att_d[4], att_s[4];
#pragma unroll
        for (int j = 0; j < 4; j++) {
            att_d[j] = att[tx * 4 + j];
            att_s[j] = att[64 + tx * 4 + j];
        }

        for (int tile = bid - BUILD_BLOCKS; tile < TILES; tile += GEMM_BLOCKS) {
            const int n0 = tile * 64;
            unsigned long long accp[4][2];
#pragma unroll
            for (int i = 0; i < 4; i++) { accp[i][0] = 0ull; accp[i][1] = 0ull; }

            for (int kc = 0; kc < IC; kc += 64) {
                for (int i = tid; i < 64 * 64; i += 256) {
                    int k = i >> 6, c = i & 63;
                    Ws[k][c] = W[(kc + k) * OC + c];
                }
                for (int i = tid; i < 64 * 64; i += 256) {
                    int r = i >> 6, k = i & 63;
                    int n = n0 + r;
                    Xs[k][r] = (n < NN) ? x[n * IC + kc + k] : 0.f;
                }
                __syncthreads();
#pragma unroll
                for (int k = 0; k < 64; k++) {
                    float4 xv = *(const float4*)&Xs[k][ty * 4];
                    const unsigned long long* wp =
                        (const unsigned long long*)&Ws[k][tx * 4];
                    unsigned long long w0 = wp[0], w1 = wp[1];
                    unsigned long long x0 = dup2(xv.x);
                    unsigned long long x1 = dup2(xv.y);
                    unsigned long long x2 = dup2(xv.z);
                    unsigned long long x3 = dup2(xv.w);
                    ffma2(accp[0][0], x0, w0); ffma2(accp[0][1], x0, w1);
                    ffma2(accp[1][0], x1, w0); ffma2(accp[1][1], x1, w1);
                    ffma2(accp[2][0], x2, w0); ffma2(accp[2][1], x2, w1);
                    ffma2(accp[3][0], x3, w0); ffma2(accp[3][1], x3, w1);
                }
                __syncthreads();
            }

#pragma unroll
            for (int i = 0; i < 4; i++) {
                float2 p0 = unpack2(accp[i][0]);
                float2 p1 = unpack2(accp[i][1]);
                int n = n0 + ty * 4 + i;
                if (n < NN) {
                    float4 v = make_float4(p0.x, p0.y, p1.x, p1.y);
                    *(float4*)(g_h + n * OC + tx * 4) = v;
                }
                float pd = p0.x * att_d[0] + p0.y * att_d[1] +
                           p1.x * att_d[2] + p1.y * att_d[3];
                float ps = p0.x * att_s[0] + p0.y * att_s[1] +
                           p1.x * att_s[2] + p1.y * att_s[3];
#pragma unroll
                for (int o = 8; o > 0; o >>= 1) {
                    pd += __shfl_down_sync(0xffffffffu, pd, o, 16);
                    ps += __shfl_down_sync(0xffffffffu, ps, o, 16);
                }
                if (tx == 0 && n < NN) {
                    g_adst[n] = pd;
                    g_asrc[n] = ps;
                }
            }
        }
    }
}

// ============================================================
// K6: fused gather + softmax + bias + L2 norm. Warp per node;
// two edges per warp-iteration (16 lanes x float4 each).
// Lane-distributed weight precompute (1 expf/edge).
// ============================================================
__global__ void k6_gather(const float* __restrict__ bias, float* __restrict__ out) {
    if (blockIdx.x == 0 && threadIdx.x < 3) {
        g_barcnt[threadIdx.x] = 0;
        g_barrel[threadIdx.x] = 0;
    }
    const int lane = threadIdx.x & 31;
    const int hw = lane >> 4;          // which edge of the pair
    const int c  = lane & 15;          // float4 column group
    const int n = blockIdx.x * 8 + (threadIdx.x >> 5);
    if (n >= NN) return;

    const float ad = g_adst[n];

    // self loop: only half-warp 0 accumulates it
    float al = ad + g_asrc[n];
    al = (al > 0.f) ? al : 0.2f * al;
    float wself = __expf(al);
    float wsum = wself;
    float4 acc = make_float4(0.f, 0.f, 0.f, 0.f);
    if (hw == 0) {
        float4 hv = *(const float4*)(g_h + n * OC + c * 4);
        acc.x = wself * hv.x; acc.y = wself * hv.y;
        acc.z = wself * hv.z; acc.w = wself * hv.w;
    }

    const int beg = g_ptr[n];
    const int end = g_ptr[n + 1];
    for (int base = beg; base < end; base += 32) {
        const int idx = base + lane;
        int s = 0;
        float w = 0.f;
        if (idx < end) {
            s = g_col[idx];                          // coalesced
            float a = ad + g_asrc[s];
            a = (a > 0.f) ? a : 0.2f * a;
            w = __expf(a);
        }
        // chunk weight sum (allreduce; inactive lanes contribute 0)
        float wtot = w;
#pragma unroll
        for (int o = 16; o > 0; o >>= 1) wtot += __shfl_xor_sync(0xffffffffu, wtot, o);
        wsum += wtot;

        const int cnt = min(32, end - base);
        const int pairs = (cnt + 1) >> 1;
        for (int j = 0; j < pairs; j++) {
            // half-warp hw takes edge 2j+hw of this chunk
            int src = 2 * j + hw;
            int  sj = __shfl_sync(0xffffffffu, s, src);
            float wj = __shfl_sync(0xffffffffu, w, src);  // 0 if past end
            float4 hv = *(const float4*)(g_h + sj * OC + c * 4);
            acc.x += wj * hv.x; acc.y += wj * hv.y;
            acc.z += wj * hv.z; acc.w += wj * hv.w;
        }
    }

    // merge the two half-warp accumulators (lanes l and l^16 share c)
    acc.x += __shfl_xor_sync(0xffffffffu, acc.x, 16);
    acc.y += __shfl_xor_sync(0xffffffffu, acc.y, 16);
    acc.z += __shfl_xor_sync(0xffffffffu, acc.z, 16);
    acc.w += __shfl_xor_sync(0xffffffffu, acc.w, 16);

    const float4 bv = *(const float4*)(bias + c * 4);
    float inv_s = 1.0f / (wsum + 1e-16f);
    float v0 = acc.x * inv_s + bv.x;
    float v1 = acc.y * inv_s + bv.y;
    float v2 = acc.z * inv_s + bv.z;
    float v3 = acc.w * inv_s + bv.w;

    // L2 norm over the 16 c-groups (halves hold identical values)
    float ss = v0 * v0 + v1 * v1 + v2 * v2 + v3 * v3;
#pragma unroll
    for (int o = 8; o > 0; o >>= 1) ss += __shfl_xor_sync(0xffffffffu, ss, o);
    float inv = 1.0f / fmaxf(sqrtf(ss), 1e-12f);
    if (hw == 0) {
        *(float4*)(out + n * OC + c * 4) =
            make_float4(v0 * inv, v1 * inv, v2 * inv, v3 * inv);
    }
}

extern "C" void kernel_launch(void* const* d_in, const int* in_sizes, int n_in,
                              void* d_out, int out_size) {
    const float* x = (const float*)d_in[0];
    const int* ei32 = (const int*)d_in[1];   // dtype sniffed on device
    const float* W = (const float*)d_in[2];
    const float* att = (const float*)d_in[3];
    const float* bias = (const float*)d_in[4];
    float* out = (float*)d_out;

    mega<<<GRID, 256>>>(x, W, att, ei32);
    k6_gather<<<(NN + 7) / 8, 256>>>(bias, out);
}

// round 14
// speedup vs baseline: 2.1862x; 1.0276x over previous
#include <cuda_runtime.h>
#include <cuda_bf16.h>

#define NN 50000
#define EE 800000
#define IC  128
#define OC  64
#define TILES ((NN + 63) / 64)        // 782 gemm tiles
#define BUILD_BLOCKS 112
#define GEMM_BLOCKS  332
#define GRID (BUILD_BLOCKS + GEMM_BLOCKS)   // 444 = 148 * 3 -> one wave
#define SCAN_BLOCKS 98                // 98 * 512 >= NN

// ---- scratch (no device allocations; zero-initialized at module load) ----
__device__ __align__(16) float g_h[NN * OC];
__device__ float g_adst[NN];
__device__ float g_asrc[NN];
__device__ int   g_deg[NN];       // zeros on entry; restored during scan
__device__ int   g_ptr[NN + 1];
__device__ int   g_cursor[NN];
__device__ int   g_col[EE];
__device__ int   g_agg[128];
__device__ int   g_barcnt[3];     // build barrier counters (reset by k6)
__device__ int   g_barrel[3];     // build barrier release flags (reset by k6)

// int64-layout sniff: ids < 2^31 => odd 32-bit words all zero
__device__ __forceinline__ bool sniff64(const int* ei32) {
    int z = (ei32[1] == 0) + (ei32[3] == 0) + (ei32[5] == 0) +
            (ei32[7] == 0) + (ei32[9] == 0) + (ei32[11] == 0);
    return z == 6;
}

// barrier among the BUILD_BLOCKS build blocks (all resident => safe spin)
__device__ __forceinline__ void build_barrier(int id) {
    __syncthreads();
    if (threadIdx.x == 0) {
        __threadfence();
        int prev = atomicAdd(&g_barcnt[id], 1);
        if (prev == BUILD_BLOCKS - 1) {
            __threadfence();
            atomicExch(&g_barrel[id], 1);
        }
        while (atomicAdd(&g_barrel[id], 0) == 0) { }
        __threadfence();
    }
    __syncthreads();
}

// packed fp32x2 FMA: d = a * b + d  (sm_100+)
__device__ __forceinline__ void ffma2(unsigned long long& d,
                                      unsigned long long a,
                                      unsigned long long b) {
    asm("fma.rn.f32x2 %0, %1, %2, %0;" : "+l"(d) : "l"(a), "l"(b));
}
__device__ __forceinline__ unsigned long long dup2(float v) {
    unsigned long long p;
    unsigned int b = __float_as_uint(v);
    asm("mov.b64 %0, {%1, %2};" : "=l"(p) : "r"(b), "r"(b));
    return p;
}
__device__ __forceinline__ float2 unpack2(unsigned long long p) {
    unsigned int lo, hi;
    asm("mov.b64 {%0, %1}, %2;" : "=r"(lo), "=r"(hi) : "l"(p));
    return make_float2(__uint_as_float(lo), __uint_as_float(hi));
}

// ============================================================
// MEGA: blocks [0,112) build full CSR; blocks [112,444) GEMM
// (h = x@W + fused attention dots), f32x2-packed FMAs.
// ============================================================
__global__ __launch_bounds__(256, 3) void mega(
    const float* __restrict__ x, const float* __restrict__ W,
    const float* __restrict__ att, const int* __restrict__ ei32)
{
    __shared__ float Ws[64][64];
    __shared__ float Xs[64][68];
    __shared__ int   ish[128];
    const int tid = threadIdx.x;
    const int bid = blockIdx.x;

    if (bid < BUILD_BLOCKS) {
        // ---------------- build role ----------------
        const bool is64 = sniff64(ei32);

        // Phase A: in-degree histogram
        for (int e = bid * 256 + tid; e < EE; e += BUILD_BLOCKS * 256) {
            int d = is64 ? ei32[2 * (EE + e)] : ei32[EE + e];
            d = min(max(d, 0), NN - 1);
            atomicAdd(&g_deg[d], 1);
        }
        build_barrier(0);

        // Phase B1: local exclusive scan (blocks 0..97, 512 elems each)
        int v0 = 0, v1 = 0, local_excl = 0;
        int i0 = 0, i1 = 0;
        if (bid < SCAN_BLOCKS) {
            const int lane = tid & 31, wid = tid >> 5;
            i0 = bid * 512 + 2 * tid;
            i1 = i0 + 1;
            v0 = (i0 < NN) ? g_deg[i0] : 0;
            v1 = (i1 < NN) ? g_deg[i1] : 0;
            if (i0 < NN) g_deg[i0] = 0;    // restore invariant
            if (i1 < NN) g_deg[i1] = 0;
            int ts = v0 + v1, s = ts;
#pragma unroll
            for (int o = 1; o < 32; o <<= 1) {
                int t = __shfl_up_sync(0xffffffffu, s, o);
                if (lane >= o) s += t;
            }
            if (lane == 31) ish[wid] = s;
            __syncthreads();
            if (wid == 0 && lane < 8) {
                int ws = ish[lane];
#pragma unroll
                for (int o = 1; o < 8; o <<= 1) {
                    int t = __shfl_up_sync(0x000000ffu, ws, o);
                    if (lane >= o) ws += t;
                }
                ish[lane] = ws;
            }
            __syncthreads();
            local_excl = (s - ts) + ((wid > 0) ? ish[wid - 1] : 0);
            if (tid == 0) g_agg[bid] = ish[7];   // single writer
            __syncthreads();
        }
        build_barrier(1);

        // Phase B2: cross-block prefix + write ptr/cursor
        if (bid < SCAN_BLOCKS) {
            if (tid < 128) ish[tid] = (tid < bid) ? g_agg[tid] : 0;
            __syncthreads();
#pragma unroll
            for (int o = 64; o > 0; o >>= 1) {
                if (tid < o) ish[tid] += ish[tid + o];
                __syncthreads();
            }
            const int prefix = ish[0];
            int e0 = prefix + local_excl;
            if (i0 < NN) { g_ptr[i0] = e0;      g_cursor[i0] = e0; }
            if (i1 < NN) { g_ptr[i1] = e0 + v0; g_cursor[i1] = e0 + v0; }
            if (bid == 0 && tid == 0) g_ptr[NN] = EE;
        }
        build_barrier(2);

        // Phase C: fill CSR columns
        for (int e = bid * 256 + tid; e < EE; e += BUILD_BLOCKS * 256) {
            int s, d;
            if (is64) { s = ei32[2 * e]; d = ei32[2 * (EE + e)]; }
            else      { s = ei32[e];     d = ei32[EE + e]; }
            s = min(max(s, 0), NN - 1);
            d = min(max(d, 0), NN - 1);
            int pos = atomicAdd(&g_cursor[d], 1);
            g_col[pos] = s;
        }
    } else {
        // ---------------- gemm role ----------------
        const int tx = tid & 15;
        const int ty = tid >> 4;

        float att_d[4], att_s[4];
#pragma unroll
        for (int j = 0; j < 4; j++) {
            att_d[j] = att[tx * 4 + j];
            att_s[j] = att[64 + tx * 4 + j];
        }

        for (int tile = bid - BUILD_BLOCKS; tile < TILES; tile += GEMM_BLOCKS) {
            const int n0 = tile * 64;
            unsigned long long accp[4][2];
#pragma unroll
            for (int i = 0; i < 4; i++) { accp[i][0] = 0ull; accp[i][1] = 0ull; }

            for (int kc = 0; kc < IC; kc += 64) {
                for (int i = tid; i < 64 * 64; i += 256) {
                    int k = i >> 6, c = i & 63;
                    Ws[k][c] = W[(kc + k) * OC + c];
                }
                for (int i = tid; i < 64 * 64; i += 256) {
                    int r = i >> 6, k = i & 63;
                    int n = n0 + r;
                    Xs[k][r] = (n < NN) ? x[n * IC + kc + k] : 0.f;
                }
                __syncthreads();
#pragma unroll
                for (int k = 0; k < 64; k++) {
                    float4 xv = *(const float4*)&Xs[k][ty * 4];
                    const unsigned long long* wp =
                        (const unsigned long long*)&Ws[k][tx * 4];
                    unsigned long long w0 = wp[0], w1 = wp[1];
                    unsigned long long x0 = dup2(xv.x);
                    unsigned long long x1 = dup2(xv.y);
                    unsigned long long x2 = dup2(xv.z);
                    unsigned long long x3 = dup2(xv.w);
                    ffma2(accp[0][0], x0, w0); ffma2(accp[0][1], x0, w1);
                    ffma2(accp[1][0], x1, w0); ffma2(accp[1][1], x1, w1);
                    ffma2(accp[2][0], x2, w0); ffma2(accp[2][1], x2, w1);
                    ffma2(accp[3][0], x3, w0); ffma2(accp[3][1], x3, w1);
                }
                __syncthreads();
            }

#pragma unroll
            for (int i = 0; i < 4; i++) {
                float2 p0 = unpack2(accp[i][0]);
                float2 p1 = unpack2(accp[i][1]);
                int n = n0 + ty * 4 + i;
                if (n < NN) {
                    float4 v = make_float4(p0.x, p0.y, p1.x, p1.y);
                    *(float4*)(g_h + n * OC + tx * 4) = v;
                }
                float pd = p0.x * att_d[0] + p0.y * att_d[1] +
                           p1.x * att_d[2] + p1.y * att_d[3];
                float ps = p0.x * att_s[0] + p0.y * att_s[1] +
                           p1.x * att_s[2] + p1.y * att_s[3];
#pragma unroll
                for (int o = 8; o > 0; o >>= 1) {
                    pd += __shfl_down_sync(0xffffffffu, pd, o, 16);
                    ps += __shfl_down_sync(0xffffffffu, ps, o, 16);
                }
                if (tx == 0 && n < NN) {
                    g_adst[n] = pd;
                    g_asrc[n] = ps;
                }
            }
        }
    }
}

// ============================================================
// K6: fused gather + softmax + bias + L2 norm. Warp per node;
// two edges per pair-slot (16 lanes x float4); pair loop
// unrolled x4 with zero-padded weights -> MLP 4.
// ============================================================
__global__ void k6_gather(const float* __restrict__ bias, float* __restrict__ out) {
    if (blockIdx.x == 0 && threadIdx.x < 3) {
        g_barcnt[threadIdx.x] = 0;
        g_barrel[threadIdx.x] = 0;
    }
    const int lane = threadIdx.x & 31;
    const int hw = lane >> 4;          // which edge of the pair
    const int c  = lane & 15;          // float4 column group
    const int n = blockIdx.x * 8 + (threadIdx.x >> 5);
    if (n >= NN) return;

    const float ad = g_adst[n];

    // self loop: only half-warp 0 accumulates it
    float al = ad + g_asrc[n];
    al = (al > 0.f) ? al : 0.2f * al;
    float wself = __expf(al);
    float4 acc = make_float4(0.f, 0.f, 0.f, 0.f);
    if (hw == 0) {
        float4 hv = *(const float4*)(g_h + n * OC + c * 4);
        acc.x = wself * hv.x; acc.y = wself * hv.y;
        acc.z = wself * hv.z; acc.w = wself * hv.w;
    }

    float wlane = 0.f;   // per-lane weight sum (reduced once at the end)

    const int beg = g_ptr[n];
    const int end = g_ptr[n + 1];
    for (int base = beg; base < end; base += 32) {
        const int idx = base + lane;
        int s = 0;
        float w = 0.f;
        if (idx < end) {
            s = g_col[idx];                          // coalesced
            float a = ad + g_asrc[s];
            a = (a > 0.f) ? a : 0.2f * a;
            w = __expf(a);
        }
        wlane += w;

        const int cnt = min(32, end - base);
        int pr = (((cnt + 1) >> 1) + 3) & ~3;        // pairs rounded up to mult of 4 (<=16)
        for (int j = 0; j < pr; j += 4) {
            int sj[4]; float wj[4];
#pragma unroll
            for (int u = 0; u < 4; u++) {
                int src = 2 * (j + u) + hw;          // <32 since j+u<16
                sj[u] = __shfl_sync(0xffffffffu, s, src);
                wj[u] = __shfl_sync(0xffffffffu, w, src);   // 0 beyond cnt
            }
            float4 h0 = *(const float4*)(g_h + sj[0] * OC + c * 4);
            float4 h1 = *(const float4*)(g_h + sj[1] * OC + c * 4);
            float4 h2 = *(const float4*)(g_h + sj[2] * OC + c * 4);
            float4 h3 = *(const float4*)(g_h + sj[3] * OC + c * 4);
            acc.x += wj[0] * h0.x; acc.y += wj[0] * h0.y;
            acc.z += wj[0] * h0.z; acc.w += wj[0] * h0.w;
            acc.x += wj[1] * h1.x; acc.y += wj[1] * h1.y;
            acc.z += wj[1] * h1.z; acc.w += wj[1] * h1.w;
            acc.x += wj[2] * h2.x; acc.y += wj[2] * h2.y;
            acc.z += wj[2] * h2.z; acc.w += wj[2] * h2.w;
            acc.x += wj[3] * h3.x; acc.y += wj[3] * h3.y;
            acc.z += wj[3] * h3.z; acc.w += wj[3] * h3.w;
        }
    }

    // single weight-sum allreduce
    float wsum = wlane;
#pragma unroll
    for (int o = 16; o > 0; o >>= 1) wsum += __shfl_xor_sync(0xffffffffu, wsum, o);
    wsum += wself;

    // merge the two half-warp accumulators (lanes l and l^16 share c)
    acc.x += __shfl_xor_sync(0xffffffffu, acc.x, 16);
    acc.y += __shfl_xor_sync(0xffffffffu, acc.y, 16);
    acc.z += __shfl_xor_sync(0xffffffffu, acc.z, 16);
    acc.w += __shfl_xor_sync(0xffffffffu, acc.w, 16);

    const float4 bv = *(const float4*)(bias + c * 4);
    float inv_s = 1.0f / (wsum + 1e-16f);
    float v0 = acc.x * inv_s + bv.x;
    float v1 = acc.y * inv_s + bv.y;
    float v2 = acc.z * inv_s + bv.z;
    float v3 = acc.w * inv_s + bv.w;

    // L2 norm over the 16 c-groups (halves hold identical values)
    float ss = v0 * v0 + v1 * v1 + v2 * v2 + v3 * v3;
#pragma unroll
    for (int o = 8; o > 0; o >>= 1) ss += __shfl_xor_sync(0xffffffffu, ss, o);
    float inv = 1.0f / fmaxf(sqrtf(ss), 1e-12f);
    if (hw == 0) {
        *(float4*)(out + n * OC + c * 4) =
            make_float4(v0 * inv, v1 * inv, v2 * inv, v3 * inv);
    }
}

extern "C" void kernel_launch(void* const* d_in, const int* in_sizes, int n_in,
                              void* d_out, int out_size) {
    const float* x = (const float*)d_in[0];
    const int* ei32 = (const int*)d_in[1];   // dtype sniffed on device
    const float* W = (const float*)d_in[2];
    const float* att = (const float*)d_in[3];
    const float* bias = (const float*)d_in[4];
    float* out = (float*)d_out;

    mega<<<GRID, 256>>>(x, W, att, ei32);
    k6_gather<<<(NN + 7) / 8, 256>>>(bias, out);
}

// round 15
// speedup vs baseline: 2.3170x; 1.0598x over previous
#include <cuda_runtime.h>
#include <cuda_bf16.h>

#define NN 50000
#define EE 800000
#define IC  128
#define OC  64
#define TILES ((NN + 63) / 64)        // 782 gemm tiles (781.25 -> 782)
#define BUILD_BLOCKS 183
#define GEMM_BLOCKS  261              // 261*3 = 783 >= 782, exactly 3 tiles each
#define GRID (BUILD_BLOCKS + GEMM_BLOCKS)   // 444 = 148 * 3 -> one wave
#define SCAN_BLOCKS 98                // 98 * 512 >= NN

// ---- scratch (no device allocations; zero-initialized at module load) ----
__device__ __align__(16) float g_h[NN * OC];
__device__ float g_adst[NN];
__device__ float g_asrc[NN];
__device__ int   g_deg[NN];       // zeros on entry; restored during scan
__device__ int   g_ptr[NN + 1];
__device__ int   g_cursor[NN];
__device__ int   g_col[EE];
__device__ int   g_agg[128];
__device__ int   g_barcnt[3];     // build barrier counters (reset by k6)
__device__ int   g_barrel[3];     // build barrier release flags (reset by k6)

// int64-layout sniff: ids < 2^31 => odd 32-bit words all zero
__device__ __forceinline__ bool sniff64(const int* ei32) {
    int z = (ei32[1] == 0) + (ei32[3] == 0) + (ei32[5] == 0) +
            (ei32[7] == 0) + (ei32[9] == 0) + (ei32[11] == 0);
    return z == 6;
}

// barrier among the BUILD_BLOCKS build blocks (all resident => safe spin)
__device__ __forceinline__ void build_barrier(int id) {
    __syncthreads();
    if (threadIdx.x == 0) {
        __threadfence();
        int prev = atomicAdd(&g_barcnt[id], 1);
        if (prev == BUILD_BLOCKS - 1) {
            __threadfence();
            atomicExch(&g_barrel[id], 1);
        }
        while (atomicAdd(&g_barrel[id], 0) == 0) { }
        __threadfence();
    }
    __syncthreads();
}

// packed fp32x2 FMA: d = a * b + d  (sm_100+)
__device__ __forceinline__ void ffma2(unsigned long long& d,
                                      unsigned long long a,
                                      unsigned long long b) {
    asm("fma.rn.f32x2 %0, %1, %2, %0;" : "+l"(d) : "l"(a), "l"(b));
}
__device__ __forceinline__ unsigned long long dup2(float v) {
    unsigned long long p;
    unsigned int b = __float_as_uint(v);
    asm("mov.b64 %0, {%1, %2};" : "=l"(p) : "r"(b), "r"(b));
    return p;
}
__device__ __forceinline__ float2 unpack2(unsigned long long p) {
    unsigned int lo, hi;
    asm("mov.b64 {%0, %1}, %2;" : "=r"(lo), "=r"(hi) : "l"(p));
    return make_float2(__uint_as_float(lo), __uint_as_float(hi));
}

// ============================================================
// MEGA: blocks [0,183) build full CSR; blocks [183,444) GEMM
// (h = x@W + fused attention dots), 3 tiles each, f32x2 FMAs.
// ============================================================
__global__ __launch_bounds__(256, 3) void mega(
    const float* __restrict__ x, const float* __restrict__ W,
    const float* __restrict__ att, const int* __restrict__ ei32)
{
    __shared__ float Ws[64][64];
    __shared__ float Xs[64][68];
    __shared__ int   ish[128];
    const int tid = threadIdx.x;
    const int bid = blockIdx.x;

    if (bid < BUILD_BLOCKS) {
        // ---------------- build role ----------------
        const bool is64 = sniff64(ei32);

        // Phase A: in-degree histogram
        for (int e = bid * 256 + tid; e < EE; e += BUILD_BLOCKS * 256) {
            int d = is64 ? ei32[2 * (EE + e)] : ei32[EE + e];
            d = min(max(d, 0), NN - 1);
            atomicAdd(&g_deg[d], 1);
        }
        build_barrier(0);

        // Phase B1: local exclusive scan (blocks 0..97, 512 elems each)
        int v0 = 0, v1 = 0, local_excl = 0;
        int i0 = 0, i1 = 0;
        if (bid < SCAN_BLOCKS) {
            const int lane = tid & 31, wid = tid >> 5;
            i0 = bid * 512 + 2 * tid;
            i1 = i0 + 1;
            v0 = (i0 < NN) ? g_deg[i0] : 0;
            v1 = (i1 < NN) ? g_deg[i1] : 0;
            if (i0 < NN) g_deg[i0] = 0;    // restore invariant
            if (i1 < NN) g_deg[i1] = 0;
            int ts = v0 + v1, s = ts;
#pragma unroll
            for (int o = 1; o < 32; o <<= 1) {
                int t = __shfl_up_sync(0xffffffffu, s, o);
                if (lane >= o) s += t;
            }
            if (lane == 31) ish[wid] = s;
            __syncthreads();
            if (wid == 0 && lane < 8) {
                int ws = ish[lane];
#pragma unroll
                for (int o = 1; o < 8; o <<= 1) {
                    int t = __shfl_up_sync(0x000000ffu, ws, o);
                    if (lane >= o) ws += t;
                }
                ish[lane] = ws;
            }
            __syncthreads();
            local_excl = (s - ts) + ((wid > 0) ? ish[wid - 1] : 0);
            if (tid == 0) g_agg[bid] = ish[7];   // single writer
            __syncthreads();
        }
        build_barrier(1);

        // Phase B2: cross-block prefix + write ptr/cursor
        if (bid < SCAN_BLOCKS) {
            if (tid < 128) ish[tid] = (tid < bid) ? g_agg[tid] : 0;
            __syncthreads();
#pragma unroll
            for (int o = 64; o > 0; o >>= 1) {
                if (tid < o) ish[tid] += ish[tid + o];
                __syncthreads();
            }
            const int prefix = ish[0];
            int e0 = prefix + local_excl;
            if (i0 < NN) { g_ptr[i0] = e0;      g_cursor[i0] = e0; }
            if (i1 < NN) { g_ptr[i1] = e0 + v0; g_cursor[i1] = e0 + v0; }
            if (bid == 0 && tid == 0) g_ptr[NN] = EE;
        }
        build_barrier(2);

        // Phase C: fill CSR columns
        for (int e = bid * 256 + tid; e < EE; e += BUILD_BLOCKS * 256) {
            int s, d;
            if (is64) { s = ei32[2 * e]; d = ei32[2 * (EE + e)]; }
            else      { s = ei32[e];     d = ei32[EE + e]; }
            s = min(max(s, 0), NN - 1);
            d = min(max(d, 0), NN - 1);
            int pos = atomicAdd(&g_cursor[d], 1);
            g_col[pos] = s;
        }
    } else {
        // ---------------- gemm role ----------------
        const int tx = tid & 15;
        const int ty = tid >> 4;

        float att_d[4], att_s[4];
#pragma unroll
        for (int j = 0; j < 4; j++) {
            att_d[j] = att[tx * 4 + j];
            att_s[j] = att[64 + tx * 4 + j];
        }

        // float4 fill indices
        const int fk = tid >> 4;            // k row 0..15 (x4 groups below)
        const int fc = (tid & 15) * 4;      // 4 consecutive columns / k's

        for (int tile = bid - BUILD_BLOCKS; tile < TILES; tile += GEMM_BLOCKS) {
            const int n0 = tile * 64;
            unsigned long long accp[4][2];
#pragma unroll
            for (int i = 0; i < 4; i++) { accp[i][0] = 0ull; accp[i][1] = 0ull; }

            for (int kc = 0; kc < IC; kc += 64) {
                // Ws fill: 4096 floats / 256 threads = 4 each (one float4)
                // thread handles k rows fk, fk+16, fk+32, fk+48 -> one f4 each
#pragma unroll
                for (int kk = 0; kk < 64; kk += 16) {
                    int k = fk + kk;
                    *(float4*)&Ws[k][fc] = *(const float4*)&W[(kc + k) * OC + fc];
                }
                // Xs fill (transposed): thread loads float4 of x row r,
                // stores 4 scalar STS. r = fk + kk, k range fc..fc+3
#pragma unroll
                for (int kk = 0; kk < 64; kk += 16) {
                    int r = fk + kk;
                    int n = n0 + r;
                    float4 xv = (n < NN) ? *(const float4*)&x[n * IC + kc + fc]
                                         : make_float4(0.f, 0.f, 0.f, 0.f);
                    Xs[fc + 0][r] = xv.x;
                    Xs[fc + 1][r] = xv.y;
                    Xs[fc + 2][r] = xv.z;
                    Xs[fc + 3][r] = xv.w;
                }
                __syncthreads();
#pragma unroll
                for (int k = 0; k < 64; k++) {
                    float4 xv = *(const float4*)&Xs[k][ty * 4];
                    const unsigned long long* wp =
                        (const unsigned long long*)&Ws[k][tx * 4];
                    unsigned long long w0 = wp[0], w1 = wp[1];
                    unsigned long long x0 = dup2(xv.x);
                    unsigned long long x1 = dup2(xv.y);
                    unsigned long long x2 = dup2(xv.z);
                    unsigned long long x3 = dup2(xv.w);
                    ffma2(accp[0][0], x0, w0); ffma2(accp[0][1], x0, w1);
                    ffma2(accp[1][0], x1, w0); ffma2(accp[1][1], x1, w1);
                    ffma2(accp[2][0], x2, w0); ffma2(accp[2][1], x2, w1);
                    ffma2(accp[3][0], x3, w0); ffma2(accp[3][1], x3, w1);
                }
                __syncthreads();
            }

#pragma unroll
            for (int i = 0; i < 4; i++) {
                float2 p0 = unpack2(accp[i][0]);
                float2 p1 = unpack2(accp[i][1]);
                int n = n0 + ty * 4 + i;
                if (n < NN) {
                    float4 v = make_float4(p0.x, p0.y, p1.x, p1.y);
                    *(float4*)(g_h + n * OC + tx * 4) = v;
                }
                float pd = p0.x * att_d[0] + p0.y * att_d[1] +
                           p1.x * att_d[2] + p1.y * att_d[3];
                float ps = p0.x * att_s[0] + p0.y * att_s[1] +
                           p1.x * att_s[2] + p1.y * att_s[3];
#pragma unroll
                for (int o = 8; o > 0; o >>= 1) {
                    pd += __shfl_down_sync(0xffffffffu, pd, o, 16);
                    ps += __shfl_down_sync(0xffffffffu, ps, o, 16);
                }
                if (tx == 0 && n < NN) {
                    g_adst[n] = pd;
                    g_asrc[n] = ps;
                }
            }
        }
    }
}

// ============================================================
// K6: fused gather + softmax + bias + L2 norm. Warp per node;
// chunk (s,w) staged in smem once, pair loop reads uniform
// LDS.64 (hw baked into address); unroll x4 -> MLP 4.
// ============================================================
__global__ void k6_gather(const float* __restrict__ bias, float* __restrict__ out) {
    __shared__ float2 stage[8][32];
    if (blockIdx.x == 0 && threadIdx.x < 3) {
        g_barcnt[threadIdx.x] = 0;
        g_barrel[threadIdx.x] = 0;
    }
    const int lane = threadIdx.x & 31;
    const int wwid = threadIdx.x >> 5;
    const int hw = lane >> 4;          // which edge of the pair
    const int c  = lane & 15;          // float4 column group
    const int n = blockIdx.x * 8 + wwid;
    if (n >= NN) return;

    const float ad = g_adst[n];

    // self loop: only half-warp 0 accumulates it
    float al = ad + g_asrc[n];
    al = (al > 0.f) ? al : 0.2f * al;
    float wself = __expf(al);
    float4 acc = make_float4(0.f, 0.f, 0.f, 0.f);
    if (hw == 0) {
        float4 hv = *(const float4*)(g_h + n * OC + c * 4);
        acc.x = wself * hv.x; acc.y = wself * hv.y;
        acc.z = wself * hv.z; acc.w = wself * hv.w;
    }

    float wlane = 0.f;   // per-lane weight sum (reduced once at the end)

    const int beg = g_ptr[n];
    const int end = g_ptr[n + 1];
    for (int base = beg; base < end; base += 32) {
        const int idx = base + lane;
        int s = 0;
        float w = 0.f;
        if (idx < end) {
            s = g_col[idx];                          // coalesced
            float a = ad + g_asrc[s];
            a = (a > 0.f) ? a : 0.2f * a;
            w = __expf(a);
        }
        wlane += w;
        stage[wwid][lane] = make_float2(__int_as_float(s), w);
        __syncwarp();

        const int cnt = min(32, end - base);
        int pr = (((cnt + 1) >> 1) + 3) & ~3;        // pairs -> mult of 4 (<=16)
        const float2* st = stage[wwid];
        for (int j = 0; j < pr; j += 4) {
            // half-warp hw reads edge 2*(j+u)+hw; uniform per half-warp
            float2 e0 = st[2 * j + hw];
            float2 e1 = st[2 * j + 2 + hw];
            float2 e2 = st[2 * j + 4 + hw];
            float2 e3 = st[2 * j + 6 + hw];
            int s0 = __float_as_int(e0.x);
            int s1 = __float_as_int(e1.x);
            int s2 = __float_as_int(e2.x);
            int s3 = __float_as_int(e3.x);
            float4 h0 = *(const float4*)(g_h + s0 * OC + c * 4);
            float4 h1 = *(const float4*)(g_h + s1 * OC + c * 4);
            float4 h2 = *(const float4*)(g_h + s2 * OC + c * 4);
            float4 h3 = *(const float4*)(g_h + s3 * OC + c * 4);
            acc.x += e0.y * h0.x; acc.y += e0.y * h0.y;
            acc.z += e0.y * h0.z; acc.w += e0.y * h0.w;
            acc.x += e1.y * h1.x; acc.y += e1.y * h1.y;
            acc.z += e1.y * h1.z; acc.w += e1.y * h1.w;
            acc.x += e2.y * h2.x; acc.y += e2.y * h2.y;
            acc.z += e2.y * h2.z; acc.w += e2.y * h2.w;
            acc.x += e3.y * h3.x; acc.y += e3.y * h3.y;
            acc.z += e3.y * h3.z; acc.w += e3.y * h3.w;
        }
        __syncwarp();   // protect stage before next chunk overwrites
    }

    // single weight-sum allreduce
    float wsum = wlane;
#pragma unroll
    for (int o = 16; o > 0; o >>= 1) wsum += __shfl_xor_sync(0xffffffffu, wsum, o);
    wsum += wself;

    // merge the two half-warp accumulators (lanes l and l^16 share c)
    acc.x += __shfl_xor_sync(0xffffffffu, acc.x, 16);
    acc.y += __shfl_xor_sync(0xffffffffu, acc.y, 16);
    acc.z += __shfl_xor_sync(0xffffffffu, acc.z, 16);
    acc.w += __shfl_xor_sync(0xffffffffu, acc.w, 16);

    const float4 bv = *(const float4*)(bias + c * 4);
    float inv_s = 1.0f / (wsum + 1e-16f);
    float v0 = acc.x * inv_s + bv.x;
    float v1 = acc.y * inv_s + bv.y;
    float v2 = acc.z * inv_s + bv.z;
    float v3 = acc.w * inv_s + bv.w;

    // L2 norm over the 16 c-groups (halves hold identical values)
    float ss = v0 * v0 + v1 * v1 + v2 * v2 + v3 * v3;
#pragma unroll
    for (int o = 8; o > 0; o >>= 1) ss += __shfl_xor_sync(0xffffffffu, ss, o);
    float inv = 1.0f / fmaxf(sqrtf(ss), 1e-12f);
    if (hw == 0) {
        *(float4*)(out + n * OC + c * 4) =
            make_float4(v0 * inv, v1 * inv, v2 * inv, v3 * inv);
    }
}

extern "C" void kernel_launch(void* const* d_in, const int* in_sizes, int n_in,
                              void* d_out, int out_size) {
    const float* x = (const float*)d_in[0];
    const int* ei32 = (const int*)d_in[1];   // dtype sniffed on device
    const float* W = (const float*)d_in[2];
    const float* att = (const float*)d_in[3];
    const float* bias = (const float*)d_in[4];
    float* out = (float*)d_out;

    mega<<<GRID, 256>>>(x, W, att, ei32);
    k6_gather<<<(NN + 7) / 8, 256>>>(bias, out);
}

// round 16
// speedup vs baseline: 2.5360x; 1.0945x over previous
#include <cuda_runtime.h>
#include <cuda_bf16.h>

#define NN 50000
#define EE 800000
#define IC  128
#define OC  64
#define TILES ((NN + 63) / 64)        // 782 gemm tiles
#define BUILD_BLOCKS 183
#define GEMM_BLOCKS  261              // 261*3 = 783 >= 782, 3 tiles each
#define GRID (BUILD_BLOCKS + GEMM_BLOCKS)   // 444 = 148 * 3 -> one wave
#define SCAN_BLOCKS 98                // 98 * 512 >= NN

// ---- scratch (no device allocations; zero-initialized at module load) ----
__device__ __align__(16) float g_h[NN * OC];
__device__ float g_adst[NN];
__device__ float g_asrc[NN];
__device__ int   g_deg[NN];       // zeros on entry; restored during scan
__device__ int   g_ptr[NN + 1];
__device__ int   g_cursor[NN];
__device__ int   g_col[EE];
__device__ int   g_agg[128];
__device__ int   g_barcnt[3];     // build barrier counters (reset by k6)
__device__ int   g_barrel[3];     // build barrier release flags (reset by k6)

// int64-layout sniff: ids < 2^31 => odd 32-bit words all zero
__device__ __forceinline__ bool sniff64(const int* ei32) {
    int z = (ei32[1] == 0) + (ei32[3] == 0) + (ei32[5] == 0) +
            (ei32[7] == 0) + (ei32[9] == 0) + (ei32[11] == 0);
    return z == 6;
}

// barrier among the BUILD_BLOCKS build blocks (all resident => safe spin)
__device__ __forceinline__ void build_barrier(int id) {
    __syncthreads();
    if (threadIdx.x == 0) {
        __threadfence();
        int prev = atomicAdd(&g_barcnt[id], 1);
        if (prev == BUILD_BLOCKS - 1) {
            __threadfence();
            atomicExch(&g_barrel[id], 1);
        }
        while (atomicAdd(&g_barrel[id], 0) == 0) { }
        __threadfence();
    }
    __syncthreads();
}

// packed fp32x2 FMA: d = a * b + d  (sm_100+)
__device__ __forceinline__ void ffma2(unsigned long long& d,
                                      unsigned long long a,
                                      unsigned long long b) {
    asm("fma.rn.f32x2 %0, %1, %2, %0;" : "+l"(d) : "l"(a), "l"(b));
}
__device__ __forceinline__ unsigned long long dup2(float v) {
    unsigned long long p;
    unsigned int b = __float_as_uint(v);
    asm("mov.b64 %0, {%1, %2};" : "=l"(p) : "r"(b), "r"(b));
    return p;
}
__device__ __forceinline__ float2 unpack2(unsigned long long p) {
    unsigned int lo, hi;
    asm("mov.b64 {%0, %1}, %2;" : "=r"(lo), "=r"(hi) : "l"(p));
    return make_float2(__uint_as_float(lo), __uint_as_float(hi));
}

// ============================================================
// MEGA: blocks [0,183) build full CSR; blocks [183,444) GEMM
// (h = x@W + fused attention dots), 3 tiles each, f32x2 FMAs.
// ============================================================
__global__ __launch_bounds__(256, 3) void mega(
    const float* __restrict__ x, const float* __restrict__ W,
    const float* __restrict__ att, const int* __restrict__ ei32)
{
    __shared__ float Ws[64][64];
    __shared__ float Xs[64][68];
    __shared__ int   ish[128];
    const int tid = threadIdx.x;
    const int bid = blockIdx.x;

    if (bid < BUILD_BLOCKS) {
        // ---------------- build role ----------------
        const bool is64 = sniff64(ei32);

        // Phase A: in-degree histogram
        for (int e = bid * 256 + tid; e < EE; e += BUILD_BLOCKS * 256) {
            int d = is64 ? ei32[2 * (EE + e)] : ei32[EE + e];
            d = min(max(d, 0), NN - 1);
            atomicAdd(&g_deg[d], 1);
        }
        build_barrier(0);

        // Phase B1: local exclusive scan (blocks 0..97, 512 elems each)
        int v0 = 0, v1 = 0, local_excl = 0;
        int i0 = 0, i1 = 0;
        if (bid < SCAN_BLOCKS) {
            const int lane = tid & 31, wid = tid >> 5;
            i0 = bid * 512 + 2 * tid;
            i1 = i0 + 1;
            v0 = (i0 < NN) ? g_deg[i0] : 0;
            v1 = (i1 < NN) ? g_deg[i1] : 0;
            if (i0 < NN) g_deg[i0] = 0;    // restore invariant
            if (i1 < NN) g_deg[i1] = 0;
            int ts = v0 + v1, s = ts;
#pragma unroll
            for (int o = 1; o < 32; o <<= 1) {
                int t = __shfl_up_sync(0xffffffffu, s, o);
                if (lane >= o) s += t;
            }
            if (lane == 31) ish[wid] = s;
            __syncthreads();
            if (wid == 0 && lane < 8) {
                int ws = ish[lane];
#pragma unroll
                for (int o = 1; o < 8; o <<= 1) {
                    int t = __shfl_up_sync(0x000000ffu, ws, o);
                    if (lane >= o) ws += t;
                }
                ish[lane] = ws;
            }
            __syncthreads();
            local_excl = (s - ts) + ((wid > 0) ? ish[wid - 1] : 0);
            if (tid == 0) g_agg[bid] = ish[7];   // single writer
            __syncthreads();
        }
        build_barrier(1);

        // Phase B2: cross-block prefix + write ptr/cursor
        if (bid < SCAN_BLOCKS) {
            if (tid < 128) ish[tid] = (tid < bid) ? g_agg[tid] : 0;
            __syncthreads();
#pragma unroll
            for (int o = 64; o > 0; o >>= 1) {
                if (tid < o) ish[tid] += ish[tid + o];
                __syncthreads();
            }
            const int prefix = ish[0];
            int e0 = prefix + local_excl;
            if (i0 < NN) { g_ptr[i0] = e0;      g_cursor[i0] = e0; }
            if (i1 < NN) { g_ptr[i1] = e0 + v0; g_cursor[i1] = e0 + v0; }
            if (bid == 0 && tid == 0) g_ptr[NN] = EE;
        }
        build_barrier(2);

        // Phase C: fill CSR columns
        for (int e = bid * 256 + tid; e < EE; e += BUILD_BLOCKS * 256) {
            int s, d;
            if (is64) { s = ei32[2 * e]; d = ei32[2 * (EE + e)]; }
            else      { s = ei32[e];     d = ei32[EE + e]; }
            s = min(max(s, 0), NN - 1);
            d = min(max(d, 0), NN - 1);
            int pos = atomicAdd(&g_cursor[d], 1);
            g_col[pos] = s;
        }
    } else {
        // ---------------- gemm role ----------------
        const int tx = tid & 15;
        const int ty = tid >> 4;

        float att_d[4], att_s[4];
#pragma unroll
        for (int j = 0; j < 4; j++) {
            att_d[j] = att[tx * 4 + j];
            att_s[j] = att[64 + tx * 4 + j];
        }

        const int fk = tid >> 4;            // k row group
        const int fc = (tid & 15) * 4;      // 4 consecutive columns / k's

        for (int tile = bid - BUILD_BLOCKS; tile < TILES; tile += GEMM_BLOCKS) {
            const int n0 = tile * 64;
            unsigned long long accp[4][2];
#pragma unroll
            for (int i = 0; i < 4; i++) { accp[i][0] = 0ull; accp[i][1] = 0ull; }

            for (int kc = 0; kc < IC; kc += 64) {
#pragma unroll
                for (int kk = 0; kk < 64; kk += 16) {
                    int k = fk + kk;
                    *(float4*)&Ws[k][fc] = *(const float4*)&W[(kc + k) * OC + fc];
                }
#pragma unroll
                for (int kk = 0; kk < 64; kk += 16) {
                    int r = fk + kk;
                    int n = n0 + r;
                    float4 xv = (n < NN) ? *(const float4*)&x[n * IC + kc + fc]
                                         : make_float4(0.f, 0.f, 0.f, 0.f);
                    Xs[fc + 0][r] = xv.x;
                    Xs[fc + 1][r] = xv.y;
                    Xs[fc + 2][r] = xv.z;
                    Xs[fc + 3][r] = xv.w;
                }
                __syncthreads();
#pragma unroll
                for (int k = 0; k < 64; k++) {
                    float4 xv = *(const float4*)&Xs[k][ty * 4];
                    const unsigned long long* wp =
                        (const unsigned long long*)&Ws[k][tx * 4];
                    unsigned long long w0 = wp[0], w1 = wp[1];
                    unsigned long long x0 = dup2(xv.x);
                    unsigned long long x1 = dup2(xv.y);
                    unsigned long long x2 = dup2(xv.z);
                    unsigned long long x3 = dup2(xv.w);
                    ffma2(accp[0][0], x0, w0); ffma2(accp[0][1], x0, w1);
                    ffma2(accp[1][0], x1, w0); ffma2(accp[1][1], x1, w1);
                    ffma2(accp[2][0], x2, w0); ffma2(accp[2][1], x2, w1);
                    ffma2(accp[3][0], x3, w0); ffma2(accp[3][1], x3, w1);
                }
                __syncthreads();
            }

#pragma unroll
            for (int i = 0; i < 4; i++) {
                float2 p0 = unpack2(accp[i][0]);
                float2 p1 = unpack2(accp[i][1]);
                int n = n0 + ty * 4 + i;
                if (n < NN) {
                    float4 v = make_float4(p0.x, p0.y, p1.x, p1.y);
                    *(float4*)(g_h + n * OC + tx * 4) = v;
                }
                float pd = p0.x * att_d[0] + p0.y * att_d[1] +
                           p1.x * att_d[2] + p1.y * att_d[3];
                float ps = p0.x * att_s[0] + p0.y * att_s[1] +
                           p1.x * att_s[2] + p1.y * att_s[3];
#pragma unroll
                for (int o = 8; o > 0; o >>= 1) {
                    pd += __shfl_down_sync(0xffffffffu, pd, o, 16);
                    ps += __shfl_down_sync(0xffffffffu, ps, o, 16);
                }
                if (tx == 0 && n < NN) {
                    g_adst[n] = pd;
                    g_asrc[n] = ps;
                }
            }
        }
    }
}

// ============================================================
// K6: fused gather + softmax + bias + L2 norm.
// ONE NODE PER HALF-WARP (lanes 0-15 node A, 16-31 node B):
// prologue/epilogue amortized over 2 nodes, zero idle lanes,
// no cross-half merge. Chunk = 16 edges/half staged in smem;
// hot loop unroll x4 (each LDG.128 covers one row per half).
// ============================================================
__global__ void k6_gather(const float* __restrict__ bias, float* __restrict__ out) {
    __shared__ float2 stage[8][32];
    if (blockIdx.x == 0 && threadIdx.x < 3) {
        g_barcnt[threadIdx.x] = 0;
        g_barrel[threadIdx.x] = 0;
    }
    const int tid = threadIdx.x;
    const int lane = tid & 31;
    const int wwid = tid >> 5;
    const int hw  = lane >> 4;                 // which half
    const int lil = lane & 15;                 // lane in half = float4 col group
    const unsigned hm = hw ? 0xFFFF0000u : 0x0000FFFFu;
    const int n = blockIdx.x * 16 + wwid * 2 + hw;   // NN = 3125*16 exactly

    const float ad = g_adst[n];

    // self loop (all 16 lanes of this half active)
    float al = ad + g_asrc[n];
    al = (al > 0.f) ? al : 0.2f * al;
    float wself = __expf(al);
    float4 hv = *(const float4*)(g_h + n * OC + lil * 4);
    float4 acc;
    acc.x = wself * hv.x; acc.y = wself * hv.y;
    acc.z = wself * hv.z; acc.w = wself * hv.w;

    float wlane = 0.f;

    const int beg = g_ptr[n];
    const int end = g_ptr[n + 1];
    const float2* st = &stage[wwid][hw * 16];
    for (int base = beg; base < end; base += 16) {
        const int idx = base + lil;
        int s = 0;
        float w = 0.f;
        if (idx < end) {
            s = g_col[idx];                    // 64B contiguous per half
            float a = ad + g_asrc[s];
            a = (a > 0.f) ? a : 0.2f * a;
            w = __expf(a);
        }
        wlane += w;
        stage[wwid][lane] = make_float2(__int_as_float(s), w);
        __syncwarp(hm);

        const int cnt = min(16, end - base);
        const int pr = (cnt + 3) & ~3;         // <=16
        for (int j = 0; j < pr; j += 4) {
            float2 e0 = st[j];
            float2 e1 = st[j + 1];
            float2 e2 = st[j + 2];
            float2 e3 = st[j + 3];
            int s0 = __float_as_int(e0.x);
            int s1 = __float_as_int(e1.x);
            int s2 = __float_as_int(e2.x);
            int s3 = __float_as_int(e3.x);
            float4 h0 = *(const float4*)(g_h + s0 * OC + lil * 4);
            float4 h1 = *(const float4*)(g_h + s1 * OC + lil * 4);
            float4 h2 = *(const float4*)(g_h + s2 * OC + lil * 4);
            float4 h3 = *(const float4*)(g_h + s3 * OC + lil * 4);
            acc.x += e0.y * h0.x; acc.y += e0.y * h0.y;
            acc.z += e0.y * h0.z; acc.w += e0.y * h0.w;
            acc.x += e1.y * h1.x; acc.y += e1.y * h1.y;
            acc.z += e1.y * h1.z; acc.w += e1.y * h1.w;
            acc.x += e2.y * h2.x; acc.y += e2.y * h2.y;
            acc.z += e2.y * h2.z; acc.w += e2.y * h2.w;
            acc.x += e3.y * h3.x; acc.y += e3.y * h3.y;
            acc.z += e3.y * h3.z; acc.w += e3.y * h3.w;
        }
        __syncwarp(hm);   // protect stage before next chunk overwrites
    }

    // weight-sum reduce within the half (offsets stay inside the half)
    float wsum = wlane;
#pragma unroll
    for (int o = 8; o > 0; o >>= 1) wsum += __shfl_xor_sync(hm, wsum, o);
    wsum += wself;

    const float4 bv = *(const float4*)(bias + lil * 4);
    float inv_s = 1.0f / (wsum + 1e-16f);
    float v0 = acc.x * inv_s + bv.x;
    float v1 = acc.y * inv_s + bv.y;
    float v2 = acc.z * inv_s + bv.z;
    float v3 = acc.w * inv_s + bv.w;

    // L2 norm over the 16 lanes of the half
    float ss = v0 * v0 + v1 * v1 + v2 * v2 + v3 * v3;
#pragma unroll
    for (int o = 8; o > 0; o >>= 1) ss += __shfl_xor_sync(hm, ss, o);
    float inv = 1.0f / fmaxf(sqrtf(ss), 1e-12f);
    *(float4*)(out + n * OC + lil * 4) =
        make_float4(v0 * inv, v1 * inv, v2 * inv, v3 * inv);
}

extern "C" void kernel_launch(void* const* d_in, const int* in_sizes, int n_in,
                              void* d_out, int out_size) {
    const float* x = (const float*)d_in[0];
    const int* ei32 = (const int*)d_in[1];   // dtype sniffed on device
    const float* W = (const float*)d_in[2];
    const float* att = (const float*)d_in[3];
    const float* bias = (const float*)d_in[4];
    float* out = (float*)d_out;

    mega<<<GRID, 256>>>(x, W, att, ei32);
    k6_gather<<<NN / 16, 256>>>(bias, out);
}